// round 8
// baseline (speedup 1.0000x reference)
#include <cuda_runtime.h>
#include <cuda_fp16.h>
#include <cstdint>

#define DIMK 768
#define MROWS 4096
#define VCOLS 50257
#define VPAD 50432            // padded vocab = 197 * 256 (even)
#define BM 128
#define BN 256
#define KC 64                 // K elems per stage: 64 half = 128B rows (SW128)
#define NCH (DIMK / KC)       // 12
#define NTILES (VPAD / BN)    // 197
#define A_STAGE_BYTES (BM * 128)      // 16 KB
#define B_STAGE_BYTES (BN * 128)      // 32 KB
#define STAGE_BYTES (A_STAGE_BYTES + B_STAGE_BYTES)
#define DSMEM (4 * STAGE_BYTES)       // 192 KB

// Scratch (device globals: allocation-free rule)
__device__ __half g_xn[(size_t)MROWS * DIMK];
__device__ __half g_wn[(size_t)VPAD * DIMK];
__device__ __half g_scr[(size_t)MROWS * VPAD];      // fp16 logits scratch
__device__ float g_partials[(size_t)MROWS * NTILES];

__device__ __forceinline__ uint32_t smem_u32(const void* p) {
    uint32_t a;
    asm("{ .reg .u64 t; cvta.to.shared.u64 t, %1; cvt.u32.u64 %0, t; }" : "=r"(a) : "l"(p));
    return a;
}
__device__ __forceinline__ uint32_t swz(uint32_t x) { return x ^ ((x >> 3) & 0x70); }

template <int N>
__device__ __forceinline__ void cpwait() {
    asm volatile("cp.async.wait_group %0;" :: "n"(N) : "memory");
}
__device__ __forceinline__ void cpcommit() {
    asm volatile("cp.async.commit_group;" ::: "memory");
}
__device__ __forceinline__ void cpasync16(uint32_t s, const void* g) {
    asm volatile("cp.async.cg.shared.global [%0], [%1], 16;" :: "r"(s), "l"(g) : "memory");
}
__device__ __forceinline__ void ldm_x4(uint32_t& r0, uint32_t& r1, uint32_t& r2,
                                       uint32_t& r3, uint32_t addr) {
    asm volatile("ldmatrix.sync.aligned.m8n8.x4.shared.b16 {%0,%1,%2,%3}, [%4];"
                 : "=r"(r0), "=r"(r1), "=r"(r2), "=r"(r3) : "r"(addr));
}

// ---------------------------------------------------------------------------
// Combined row L2-normalize for x (rows < MROWS) and vocab (rest), fp16 out.
// ---------------------------------------------------------------------------
__global__ void norm_rows_kernel(const float* __restrict__ x,
                                 const float* __restrict__ wv) {
    const int b = blockIdx.x;
    const float* p;
    __half* q;
    if (b < MROWS) {
        p = x + (size_t)b * DIMK;
        q = g_xn + (size_t)b * DIMK;
    } else {
        int r = b - MROWS;
        q = g_wn + (size_t)r * DIMK;
        if (r >= VCOLS) {
            for (int i = threadIdx.x; i < DIMK; i += 256) q[i] = __float2half(0.f);
            return;
        }
        p = wv + (size_t)r * DIMK;
    }
    float s = 0.f;
    for (int i = threadIdx.x; i < DIMK; i += 256) { float v = p[i]; s += v * v; }
    for (int o = 16; o; o >>= 1) s += __shfl_xor_sync(0xffffffffu, s, o);
    __shared__ float sm[8];
    if ((threadIdx.x & 31) == 0) sm[threadIdx.x >> 5] = s;
    __syncthreads();
    if (threadIdx.x < 8) {
        float t = sm[threadIdx.x];
        for (int o = 4; o; o >>= 1) t += __shfl_xor_sync(0xffu, t, o);
        if (threadIdx.x == 0) sm[0] = t;
    }
    __syncthreads();
    float scale = 1.f / fmaxf(sqrtf(sm[0]), 1e-12f);
    for (int i = threadIdx.x; i < DIMK; i += 256)
        q[i] = __float2half(p[i] * scale);
}

// ---------------------------------------------------------------------------
// fp16 GEMM: m16n8k16 f16.f16.f16.f16 (double-rate) + ldmatrix + 4-stage
// cp.async. fp16 accumulate within each K=64 chunk, promoted to fp32 per
// chunk. 128x256 tile / CTA, 256 thr (2Mx4N warps).
// ---------------------------------------------------------------------------
__global__ void __launch_bounds__(256, 1) gemm_kernel() {
    extern __shared__ __align__(1024) char smem[];

    const int tid = threadIdx.x;
    const int w = tid >> 5, lane = tid & 31;
    const int wm = w >> 2, wn = w & 3;     // 2 x 4 warp grid
    const int m0 = blockIdx.x * BM;        // m fastest: L2-friendly waves
    const int n0 = blockIdx.y * BN;
    const uint32_t sbase = smem_u32(smem);

    const __half* Ag = g_xn + (size_t)m0 * DIMK;
    const __half* Bg = g_wn + (size_t)n0 * DIMK;

    auto load_chunk = [&](int slot, int k0) {
        uint32_t sA = sbase + slot * STAGE_BYTES;
        uint32_t sB = sA + A_STAGE_BYTES;
#pragma unroll
        for (int i = 0; i < 4; i++) {
            int s = i * 256 + tid;
            int row = s >> 3, seg = s & 7;
            cpasync16(sA + swz(row * 128 + seg * 16),
                      Ag + (size_t)row * DIMK + k0 + seg * 8);
        }
#pragma unroll
        for (int i = 0; i < 8; i++) {
            int s = i * 256 + tid;
            int row = s >> 3, seg = s & 7;
            cpasync16(sB + swz(row * 128 + seg * 16),
                      Bg + (size_t)row * DIMK + k0 + seg * 8);
        }
        cpcommit();
    };

    float acc[4][8][4];
#pragma unroll
    for (int a = 0; a < 4; a++)
#pragma unroll
        for (int b = 0; b < 8; b++)
#pragma unroll
            for (int c = 0; c < 4; c++) acc[a][b][c] = 0.f;

    uint32_t aoff[4], boff[4];
#pragma unroll
    for (int mt = 0; mt < 4; mt++)
        aoff[mt] = (uint32_t)(wm * 64 + mt * 16 + (lane & 15)) * 128;
#pragma unroll
    for (int p = 0; p < 4; p++)
        boff[p] = (uint32_t)(wn * 64 + p * 16 + (lane & 7) + ((lane >> 4) & 1) * 8) * 128;
    const uint32_t acol = ((uint32_t)(lane >> 4)) * 16;
    const uint32_t bcol = ((uint32_t)((lane >> 3) & 1)) * 16;

    load_chunk(0, 0);
    load_chunk(1, KC);
    load_chunk(2, 2 * KC);

#pragma unroll 1
    for (int c = 0; c < NCH; c++) {
        if (c + 3 < NCH) load_chunk((c + 3) & 3, (c + 3) * KC);
        if (c <= 8) cpwait<3>();
        else if (c == 9) cpwait<2>();
        else if (c == 10) cpwait<1>();
        else cpwait<0>();
        __syncthreads();

        const uint32_t sA = sbase + (c & 3) * STAGE_BYTES;
        const uint32_t sB = sA + A_STAGE_BYTES;

        uint32_t hacc[4][8][2];    // per-chunk fp16x2 accumulators

#pragma unroll
        for (int step = 0; step < KC / 16; step++) {
            const uint32_t kb = (uint32_t)step * 32;
            uint32_t af[4][4], bf[4][4];
#pragma unroll
            for (int mt = 0; mt < 4; mt++)
                ldm_x4(af[mt][0], af[mt][1], af[mt][2], af[mt][3],
                       sA + swz(aoff[mt] + kb + acol));
#pragma unroll
            for (int p = 0; p < 4; p++)
                ldm_x4(bf[p][0], bf[p][1], bf[p][2], bf[p][3],
                       sB + swz(boff[p] + kb + bcol));
#pragma unroll
            for (int mt = 0; mt < 4; mt++)
#pragma unroll
                for (int nt = 0; nt < 8; nt++) {
                    const int p = nt >> 1, sub = (nt & 1) * 2;
                    if (step == 0) {
                        asm volatile(
                            "mma.sync.aligned.m16n8k16.row.col.f16.f16.f16.f16 "
                            "{%0,%1}, {%2,%3,%4,%5}, {%6,%7}, {%8,%8};\n"
                            : "=r"(hacc[mt][nt][0]), "=r"(hacc[mt][nt][1])
                            : "r"(af[mt][0]), "r"(af[mt][1]), "r"(af[mt][2]), "r"(af[mt][3]),
                              "r"(bf[p][sub]), "r"(bf[p][sub + 1]), "r"(0u));
                    } else {
                        asm volatile(
                            "mma.sync.aligned.m16n8k16.row.col.f16.f16.f16.f16 "
                            "{%0,%1}, {%2,%3,%4,%5}, {%6,%7}, {%0,%1};\n"
                            : "+r"(hacc[mt][nt][0]), "+r"(hacc[mt][nt][1])
                            : "r"(af[mt][0]), "r"(af[mt][1]), "r"(af[mt][2]), "r"(af[mt][3]),
                              "r"(bf[p][sub]), "r"(bf[p][sub + 1]));
                    }
                }
        }

        // Promote chunk fp16 sums into fp32 accumulators (fma pipe, hidden).
#pragma unroll
        for (int mt = 0; mt < 4; mt++)
#pragma unroll
            for (int nt = 0; nt < 8; nt++) {
                float2 lo = __half22float2(*(__half2*)&hacc[mt][nt][0]);
                float2 hi = __half22float2(*(__half2*)&hacc[mt][nt][1]);
                acc[mt][nt][0] += lo.x;
                acc[mt][nt][1] += lo.y;
                acc[mt][nt][2] += hi.x;
                acc[mt][nt][3] += hi.y;
            }
        __syncthreads();
    }

    // ---- Epilogue: half2 logits to scratch + exp partials ----
    float* red = (float*)smem;     // 128 rows x 16 slots
    const int g = lane >> 2, tig = lane & 3;
#pragma unroll
    for (int mt = 0; mt < 4; mt++)
#pragma unroll
        for (int i = 0; i < 2; i++) {
            float rp = 0.f;
            const int lr = wm * 64 + mt * 16 + g + 8 * i;
            const size_t rb = (size_t)(m0 + lr) * VPAD;
#pragma unroll
            for (int nt = 0; nt < 8; nt++) {
                const int gcol = n0 + wn * 64 + nt * 8 + 2 * tig;  // even
                float l0 = acc[mt][nt][i * 2] * 20.f;
                float l1 = acc[mt][nt][i * 2 + 1] * 20.f;
                __stcs((__half2*)(g_scr + rb + gcol), __floats2half2_rn(l0, l1));
                if (gcol < VCOLS)     rp += __expf(l0 - 20.f);
                if (gcol + 1 < VCOLS) rp += __expf(l1 - 20.f);
            }
            red[lr * 16 + wn * 4 + tig] = rp;
        }
    __syncthreads();
    if (tid < 128) {
        float s = 0.f;
#pragma unroll
        for (int j = 0; j < 16; j++) s += red[tid * 16 + j];
        g_partials[(size_t)(m0 + tid) * NTILES + blockIdx.y] = s;
    }
}

// ---------------------------------------------------------------------------
// Fixup: one block per row. Inline LSE reduce, then
// out[row,col] = scr[row,col] - lse + bias[col], single fp32 write.
// ---------------------------------------------------------------------------
__global__ void __launch_bounds__(256) fixup_kernel(float* __restrict__ out,
                                                    const float* __restrict__ bias) {
    const int row = blockIdx.x;
    const int tid = threadIdx.x;

    float s = 0.f;
    const float* pp = &g_partials[(size_t)row * NTILES];
    for (int j = tid; j < NTILES; j += 256) s += pp[j];
    for (int o = 16; o; o >>= 1) s += __shfl_xor_sync(0xffffffffu, s, o);
    __shared__ float sm[8];
    if ((tid & 31) == 0) sm[tid >> 5] = s;
    __syncthreads();
    if (tid < 8) {
        float t = sm[tid];
        for (int o = 4; o; o >>= 1) t += __shfl_xor_sync(0xffu, t, o);
        if (tid == 0) sm[0] = 20.f + logf(t);
    }
    __syncthreads();
    const float lse = sm[0];

    const __half* ps = g_scr + (size_t)row * VPAD;
    float* po = out + (size_t)row * VCOLS;
#pragma unroll 2
    for (int c2 = tid; c2 * 2 < VCOLS; c2 += 256) {
        const int col = c2 * 2;
        __half2 h = __ldcs((const __half2*)(ps + col));
        float2 v = __half22float2(h);
        po[col] = v.x - lse + bias[col];
        if (col + 1 < VCOLS) po[col + 1] = v.y - lse + bias[col + 1];
    }
}

extern "C" void kernel_launch(void* const* d_in, const int* in_sizes, int n_in,
                              void* d_out, int out_size) {
    const float* x    = (const float*)d_in[0];  // [2,2048,768]
    const float* wv   = (const float*)d_in[1];  // [50257,768]
    const float* bias = (const float*)d_in[2];  // [50257]
    float* out = (float*)d_out;                 // [2,2048,50257] fp32

    cudaFuncSetAttribute(gemm_kernel, cudaFuncAttributeMaxDynamicSharedMemorySize, DSMEM);

    norm_rows_kernel<<<MROWS + VPAD, 256>>>(x, wv);
    gemm_kernel<<<dim3(MROWS / BM, NTILES), 256, DSMEM>>>();
    fixup_kernel<<<MROWS, 256>>>(out, bias);
}

// round 9
// speedup vs baseline: 1.2323x; 1.2323x over previous
#include <cuda_runtime.h>
#include <cuda_fp16.h>
#include <cstdint>

#define DIMK 768
#define MROWS 4096
#define VCOLS 50257
#define VPAD 50432            // padded vocab = 197 * 256 (even)
#define BM 128
#define BN 256
#define KC 64                 // K elems per stage: 64 half = 128B rows (SW128)
#define NCH (DIMK / KC)       // 12
#define NTILES (VPAD / BN)    // 197
#define A_STAGE_BYTES (BM * 128)      // 16 KB
#define B_STAGE_BYTES (BN * 128)      // 32 KB
#define STAGE_BYTES (A_STAGE_BYTES + B_STAGE_BYTES)
#define DSMEM (4 * STAGE_BYTES)       // 192 KB

// Scratch (device globals: allocation-free rule)
__device__ __half g_xn[(size_t)MROWS * DIMK];
__device__ __half g_wn[(size_t)VPAD * DIMK];
__device__ __half g_scr[(size_t)MROWS * VPAD];      // fp16 logits scratch
__device__ float g_partials[(size_t)MROWS * NTILES];

__device__ __forceinline__ uint32_t smem_u32(const void* p) {
    uint32_t a;
    asm("{ .reg .u64 t; cvta.to.shared.u64 t, %1; cvt.u32.u64 %0, t; }" : "=r"(a) : "l"(p));
    return a;
}
__device__ __forceinline__ uint32_t swz(uint32_t x) { return x ^ ((x >> 3) & 0x70); }

template <int N>
__device__ __forceinline__ void cpwait() {
    asm volatile("cp.async.wait_group %0;" :: "n"(N) : "memory");
}
__device__ __forceinline__ void cpcommit() {
    asm volatile("cp.async.commit_group;" ::: "memory");
}
__device__ __forceinline__ void cpasync16(uint32_t s, const void* g) {
    asm volatile("cp.async.cg.shared.global [%0], [%1], 16;" :: "r"(s), "l"(g) : "memory");
}
__device__ __forceinline__ void ldm_x4(uint32_t& r0, uint32_t& r1, uint32_t& r2,
                                       uint32_t& r3, uint32_t addr) {
    asm volatile("ldmatrix.sync.aligned.m8n8.x4.shared.b16 {%0,%1,%2,%3}, [%4];"
                 : "=r"(r0), "=r"(r1), "=r"(r2), "=r"(r3) : "r"(addr));
}

// ---------------------------------------------------------------------------
// Row L2-normalize: 4 rows/block, 64 threads/row, 3x float4 per thread,
// single pass (values held in registers), vectorized half stores.
// Row index < MROWS -> x ; else vocab (zeros past VCOLS).
// ---------------------------------------------------------------------------
__global__ void __launch_bounds__(256) norm_rows_kernel(const float* __restrict__ x,
                                                        const float* __restrict__ wv) {
    const int tid = threadIdx.x;
    const int sub = tid >> 6;            // row within block: 0..3
    const int l64 = tid & 63;            // lane within row-group
    const int row = blockIdx.x * 4 + sub;

    const float* p;
    __half* q;
    bool zero = false;
    if (row < MROWS) {
        p = x + (size_t)row * DIMK;
        q = g_xn + (size_t)row * DIMK;
    } else {
        int r = row - MROWS;
        q = g_wn + (size_t)r * DIMK;
        p = wv + (size_t)r * DIMK;
        zero = (r >= VCOLS);
    }

    float4 v[3];
    float s = 0.f;
    if (!zero) {
#pragma unroll
        for (int j = 0; j < 3; j++) {
            v[j] = *(const float4*)(p + j * 256 + l64 * 4);
            s += v[j].x * v[j].x + v[j].y * v[j].y + v[j].z * v[j].z + v[j].w * v[j].w;
        }
    } else {
#pragma unroll
        for (int j = 0; j < 3; j++) v[j] = make_float4(0.f, 0.f, 0.f, 0.f);
    }
    // reduce over 64 threads: warp shfl + pair via smem
    for (int o = 16; o; o >>= 1) s += __shfl_xor_sync(0xffffffffu, s, o);
    __shared__ float sm[8];
    if ((tid & 31) == 0) sm[tid >> 5] = s;
    __syncthreads();
    const float tot = sm[sub * 2] + sm[sub * 2 + 1];
    const float scale = zero ? 0.f : (1.f / fmaxf(sqrtf(tot), 1e-12f));

#pragma unroll
    for (int j = 0; j < 3; j++) {
        __half2 h0 = __floats2half2_rn(v[j].x * scale, v[j].y * scale);
        __half2 h1 = __floats2half2_rn(v[j].z * scale, v[j].w * scale);
        uint2 pk = make_uint2(*(uint32_t*)&h0, *(uint32_t*)&h1);
        *(uint2*)(q + j * 256 + l64 * 4) = pk;       // 8B-aligned store
    }
}

// ---------------------------------------------------------------------------
// fp16 GEMM: m16n8k16 f32.f16.f16.f32 + ldmatrix + 4-stage cp.async +
// register-level fragment double-buffering. 128x256 tile / CTA, 256 thr.
// Epilogue: half2 logits -> g_scr (evict-first), exp partials -> g_partials.
// ---------------------------------------------------------------------------
__global__ void __launch_bounds__(256, 1) gemm_kernel() {
    extern __shared__ __align__(1024) char smem[];

    const int tid = threadIdx.x;
    const int w = tid >> 5, lane = tid & 31;
    const int wm = w >> 2, wn = w & 3;     // 2 x 4 warp grid
    const int m0 = blockIdx.x * BM;        // m fastest: L2-friendly waves
    const int n0 = blockIdx.y * BN;
    const uint32_t sbase = smem_u32(smem);

    const __half* Ag = g_xn + (size_t)m0 * DIMK;
    const __half* Bg = g_wn + (size_t)n0 * DIMK;

    auto load_chunk = [&](int slot, int k0) {
        uint32_t sA = sbase + slot * STAGE_BYTES;
        uint32_t sB = sA + A_STAGE_BYTES;
#pragma unroll
        for (int i = 0; i < 4; i++) {
            int s = i * 256 + tid;
            int row = s >> 3, seg = s & 7;
            cpasync16(sA + swz(row * 128 + seg * 16),
                      Ag + (size_t)row * DIMK + k0 + seg * 8);
        }
#pragma unroll
        for (int i = 0; i < 8; i++) {
            int s = i * 256 + tid;
            int row = s >> 3, seg = s & 7;
            cpasync16(sB + swz(row * 128 + seg * 16),
                      Bg + (size_t)row * DIMK + k0 + seg * 8);
        }
        cpcommit();
    };

    float acc[4][8][4];
#pragma unroll
    for (int a = 0; a < 4; a++)
#pragma unroll
        for (int b = 0; b < 8; b++)
#pragma unroll
            for (int c = 0; c < 4; c++) acc[a][b][c] = 0.f;

    uint32_t aoff[4], boff[4];
#pragma unroll
    for (int mt = 0; mt < 4; mt++)
        aoff[mt] = (uint32_t)(wm * 64 + mt * 16 + (lane & 15)) * 128;
#pragma unroll
    for (int p = 0; p < 4; p++)
        boff[p] = (uint32_t)(wn * 64 + p * 16 + (lane & 7) + ((lane >> 4) & 1) * 8) * 128;
    const uint32_t acol = ((uint32_t)(lane >> 4)) * 16;
    const uint32_t bcol = ((uint32_t)((lane >> 3) & 1)) * 16;

    uint32_t afr[2][4][4], bfr[2][4][4];

    load_chunk(0, 0);
    load_chunk(1, KC);
    load_chunk(2, 2 * KC);

#pragma unroll 1
    for (int c = 0; c < NCH; c++) {
        if (c + 3 < NCH) load_chunk((c + 3) & 3, (c + 3) * KC);
        if (c <= 8) cpwait<3>();
        else if (c == 9) cpwait<2>();
        else if (c == 10) cpwait<1>();
        else cpwait<0>();
        __syncthreads();

        const uint32_t sA = sbase + (c & 3) * STAGE_BYTES;
        const uint32_t sB = sA + A_STAGE_BYTES;

#pragma unroll
        for (int mt = 0; mt < 4; mt++)
            ldm_x4(afr[0][mt][0], afr[0][mt][1], afr[0][mt][2], afr[0][mt][3],
                   sA + swz(aoff[mt] + acol));
#pragma unroll
        for (int p = 0; p < 4; p++)
            ldm_x4(bfr[0][p][0], bfr[0][p][1], bfr[0][p][2], bfr[0][p][3],
                   sB + swz(boff[p] + bcol));

#pragma unroll
        for (int step = 0; step < KC / 16; step++) {
            const int cur = step & 1;
            if (step < KC / 16 - 1) {
                const int nxt = cur ^ 1;
                const uint32_t kb = (uint32_t)(step + 1) * 32;
#pragma unroll
                for (int mt = 0; mt < 4; mt++)
                    ldm_x4(afr[nxt][mt][0], afr[nxt][mt][1], afr[nxt][mt][2], afr[nxt][mt][3],
                           sA + swz(aoff[mt] + kb + acol));
#pragma unroll
                for (int p = 0; p < 4; p++)
                    ldm_x4(bfr[nxt][p][0], bfr[nxt][p][1], bfr[nxt][p][2], bfr[nxt][p][3],
                           sB + swz(boff[p] + kb + bcol));
            }
#pragma unroll
            for (int mt = 0; mt < 4; mt++)
#pragma unroll
                for (int nt = 0; nt < 8; nt++) {
                    const int p = nt >> 1, sub = (nt & 1) * 2;
                    asm volatile(
                        "mma.sync.aligned.m16n8k16.row.col.f32.f16.f16.f32 "
                        "{%0,%1,%2,%3}, {%4,%5,%6,%7}, {%8,%9}, {%0,%1,%2,%3};\n"
                        : "+f"(acc[mt][nt][0]), "+f"(acc[mt][nt][1]),
                          "+f"(acc[mt][nt][2]), "+f"(acc[mt][nt][3])
                        : "r"(afr[cur][mt][0]), "r"(afr[cur][mt][1]),
                          "r"(afr[cur][mt][2]), "r"(afr[cur][mt][3]),
                          "r"(bfr[cur][p][sub]), "r"(bfr[cur][p][sub + 1]));
                }
        }
        __syncthreads();
    }

    // ---- Epilogue: half2 logits to scratch + exp partials ----
    float* red = (float*)smem;     // 128 rows x 16 slots
    const int g = lane >> 2, tig = lane & 3;
#pragma unroll
    for (int mt = 0; mt < 4; mt++)
#pragma unroll
        for (int i = 0; i < 2; i++) {
            float rp = 0.f;
            const int lr = wm * 64 + mt * 16 + g + 8 * i;
            const size_t rb = (size_t)(m0 + lr) * VPAD;
#pragma unroll
            for (int nt = 0; nt < 8; nt++) {
                const int gcol = n0 + wn * 64 + nt * 8 + 2 * tig;  // even
                float l0 = acc[mt][nt][i * 2] * 20.f;
                float l1 = acc[mt][nt][i * 2 + 1] * 20.f;
                __stcs((__half2*)(g_scr + rb + gcol), __floats2half2_rn(l0, l1));
                if (gcol < VCOLS)     rp += __expf(l0 - 20.f);
                if (gcol + 1 < VCOLS) rp += __expf(l1 - 20.f);
            }
            red[lr * 16 + wn * 4 + tig] = rp;
        }
    __syncthreads();
    if (tid < 128) {
        float s = 0.f;
#pragma unroll
        for (int j = 0; j < 16; j++) s += red[tid * 16 + j];
        g_partials[(size_t)(m0 + tid) * NTILES + blockIdx.y] = s;
    }
}

// ---------------------------------------------------------------------------
// Fixup: one block per row. Inline LSE reduce, then
// out = scr - lse + bias with alignment-headed float4 stores.
// ---------------------------------------------------------------------------
__global__ void __launch_bounds__(256) fixup_kernel(float* __restrict__ out,
                                                    const float* __restrict__ bias) {
    const int row = blockIdx.x;
    const int tid = threadIdx.x;

    // LSE = 20 + log(sum partials)
    float s = 0.f;
    const float* pp = &g_partials[(size_t)row * NTILES];
    for (int j = tid; j < NTILES; j += 256) s += pp[j];
    for (int o = 16; o; o >>= 1) s += __shfl_xor_sync(0xffffffffu, s, o);
    __shared__ float sm[8];
    if ((tid & 31) == 0) sm[tid >> 5] = s;
    __syncthreads();
    if (tid < 8) {
        float t = sm[tid];
        for (int o = 4; o; o >>= 1) t += __shfl_xor_sync(0xffu, t, o);
        if (tid == 0) sm[0] = 20.f + logf(t);
    }
    __syncthreads();
    const float lse = sm[0];

    const __half* ps = g_scr + (size_t)row * VPAD;
    float* po = out + (size_t)row * VCOLS;

    // head: #scalar cols until po+head is 16B aligned
    const int head = (4 - (int)(((uintptr_t)po >> 2) & 3)) & 3;
    if (tid < head)
        po[tid] = __half2float(ps[tid]) - lse + bias[tid];
    const int count4 = (VCOLS - head) >> 2;
    const int tail0 = head + count4 * 4;
    if (tid < VCOLS - tail0) {
        const int col = tail0 + tid;
        po[col] = __half2float(ps[col]) - lse + bias[col];
    }

    if ((head & 1) == 0) {
        // scratch cols even: half2 loads
#pragma unroll 2
        for (int i = tid; i < count4; i += 256) {
            const int col = head + i * 4;
            float2 a = __half22float2(*(const __half2*)(ps + col));
            float2 b = __half22float2(*(const __half2*)(ps + col + 2));
            float4 o4;
            o4.x = a.x - lse + __ldg(bias + col);
            o4.y = a.y - lse + __ldg(bias + col + 1);
            o4.z = b.x - lse + __ldg(bias + col + 2);
            o4.w = b.y - lse + __ldg(bias + col + 3);
            *(float4*)(po + col) = o4;
        }
    } else {
        // odd head: scalar half loads, vector store
#pragma unroll 2
        for (int i = tid; i < count4; i += 256) {
            const int col = head + i * 4;
            float4 o4;
            o4.x = __half2float(ps[col])     - lse + __ldg(bias + col);
            o4.y = __half2float(ps[col + 1]) - lse + __ldg(bias + col + 1);
            o4.z = __half2float(ps[col + 2]) - lse + __ldg(bias + col + 2);
            o4.w = __half2float(ps[col + 3]) - lse + __ldg(bias + col + 3);
            *(float4*)(po + col) = o4;
        }
    }
}

extern "C" void kernel_launch(void* const* d_in, const int* in_sizes, int n_in,
                              void* d_out, int out_size) {
    const float* x    = (const float*)d_in[0];  // [2,2048,768]
    const float* wv   = (const float*)d_in[1];  // [50257,768]
    const float* bias = (const float*)d_in[2];  // [50257]
    float* out = (float*)d_out;                 // [2,2048,50257] fp32

    cudaFuncSetAttribute(gemm_kernel, cudaFuncAttributeMaxDynamicSharedMemorySize, DSMEM);

    norm_rows_kernel<<<(MROWS + VPAD) / 4, 256>>>(x, wv);
    gemm_kernel<<<dim3(MROWS / BM, NTILES), 256, DSMEM>>>();
    fixup_kernel<<<MROWS, 256>>>(out, bias);
}